// round 12
// baseline (speedup 1.0000x reference)
#include <cuda_runtime.h>
#include <cstdint>

// Haar inverse DWT2 (db1), fp32.  Inputs A,H,V,D: [8,32,256,256]; out: [8,32,512,512].
// x[2i,2j]=(A+H+V+D)/2; x[2i,2j+1]=(A+H-V-D)/2; x[2i+1,2j]=(A-H+V-D)/2; x[2i+1,2j+1]=(A-H-V+D)/2
//
// R12 probe: persistent grid-stride variant of the R4 champion.
// Identical per-iteration dataflow (4x LDG.64, 2x STG.128, same coalescing),
// but grid = 592 CTAs (148 SM x 4 CTA) living for the whole kernel: removes
// the 28 waves of CTA drain/launch churn; iteration i+1 loads overlap
// iteration i store drain within each CTA.

#define NBLOCKS 592u   // 148 SMs * 4 CTAs of 512 thr (2048 thr/SM)

__global__ void __launch_bounds__(512) idwt2_haar_kernel(
    const float2* __restrict__ A,
    const float2* __restrict__ H,
    const float2* __restrict__ V,
    const float2* __restrict__ D,
    float4* __restrict__ out,
    unsigned total)             // total float2 work items = 8,388,608
{
    const unsigned stride = NBLOCKS * 512u;

    for (unsigned t = blockIdx.x * 512u + threadIdx.x; t < total; t += stride) {
        const float2 a = __ldg(&A[t]);
        const float2 h = __ldg(&H[t]);
        const float2 v = __ldg(&V[t]);
        const float2 d = __ldg(&D[t]);

        float lp0 = a.x + h.x, lm0 = a.x - h.x;
        float mp0 = v.x + d.x, mm0 = v.x - d.x;
        float lp1 = a.y + h.y, lm1 = a.y - h.y;
        float mp1 = v.y + d.y, mm1 = v.y - d.y;

        float4 even, odd;
        even.x = (lp0 + mp0) * 0.5f;
        even.y = (lp0 - mp0) * 0.5f;
        even.z = (lp1 + mp1) * 0.5f;
        even.w = (lp1 - mp1) * 0.5f;
        odd.x  = (lm0 + mm0) * 0.5f;
        odd.y  = (lm0 - mm0) * 0.5f;
        odd.z  = (lm1 + mm1) * 0.5f;
        odd.w  = (lm1 - mm1) * 0.5f;

        // t = b*32768 + i*128 + j2 ; even-row out f4 index = ((t>>7)<<8) + (t&127)
        const unsigned o = ((t >> 7) << 8) + (t & 127u);
        out[o]        = even;
        out[o + 128u] = odd;   // odd row: +512 floats = +128 float4s
    }
}

extern "C" void kernel_launch(void* const* d_in, const int* in_sizes, int n_in,
                              void* d_out, int out_size)
{
    const float2* A = (const float2*)d_in[0];
    const float2* H = (const float2*)d_in[1];
    const float2* V = (const float2*)d_in[2];
    const float2* D = (const float2*)d_in[3];
    float4* out = (float4*)d_out;

    const unsigned total = (unsigned)(in_sizes[0] / 2);  // 8,388,608

    idwt2_haar_kernel<<<NBLOCKS, 512>>>(A, H, V, D, out, total);
}

// round 13
// speedup vs baseline: 1.1136x; 1.1136x over previous
#include <cuda_runtime.h>
#include <cstdint>

// Haar inverse DWT2 (db1), fp32.  Inputs A,H,V,D: [8,32,256,256]; out: [8,32,512,512].
// x[2i,2j]=(A+H+V+D)/2; x[2i,2j+1]=(A+H-V-D)/2; x[2i+1,2j]=(A-H+V-D)/2; x[2i+1,2j+1]=(A-H-V+D)/2
//
// FINAL (R4 champion, locked after 12-round search):
//   one thread per float2 of input -> 4x LDG.64 + 2x STG.128, 18 regs, block=512,
//   short-lived CTAs each retiring one contiguous 16KB output chunk.
//   ~7.3 TB/s effective (~91% of 8 TB/s HBM spec) on the 50/50 R/W mix:
//   bus-turnaround-limited ceiling for this zero-reuse butterfly.
// Measured single-variable bracketing:
//   load width 128-bit    -> -6%  (L1tex wavefront doubling; R2)
//   per-thread work x2    -> tie  (issue never the limiter; R9)
//   block 256 / 1024      -> -1% / -2% (locality-vs-concurrency peak at 512)
//   .cs load/store hints  -> neutral-to-negative (R3/R6)
//   persistent grid-stride-> -12% (destroys per-SM DRAM burst locality; R12)
//   noise band            -> +/-1.5 us (R7/R8/R11 identity re-benches)

__global__ void __launch_bounds__(512) idwt2_haar_kernel(
    const float2* __restrict__ A,
    const float2* __restrict__ H,
    const float2* __restrict__ V,
    const float2* __restrict__ D,
    float4* __restrict__ out)
{
    // total threads = 8*32*256*256 / 2 = 8,388,608
    const unsigned t = blockIdx.x * 512u + threadIdx.x;

    const float2 a = __ldg(&A[t]);
    const float2 h = __ldg(&H[t]);
    const float2 v = __ldg(&V[t]);
    const float2 d = __ldg(&D[t]);

    float lp0 = a.x + h.x, lm0 = a.x - h.x;
    float mp0 = v.x + d.x, mm0 = v.x - d.x;
    float lp1 = a.y + h.y, lm1 = a.y - h.y;
    float mp1 = v.y + d.y, mm1 = v.y - d.y;

    float4 even, odd;
    even.x = (lp0 + mp0) * 0.5f;
    even.y = (lp0 - mp0) * 0.5f;
    even.z = (lp1 + mp1) * 0.5f;
    even.w = (lp1 - mp1) * 0.5f;
    odd.x  = (lm0 + mm0) * 0.5f;
    odd.y  = (lm0 - mm0) * 0.5f;
    odd.z  = (lm1 + mm1) * 0.5f;
    odd.w  = (lm1 - mm1) * 0.5f;

    // t = b*32768 + i*128 + j2 ; even-row out f4 index = ((t>>7)<<8) + (t&127)
    const unsigned o = ((t >> 7) << 8) + (t & 127u);
    out[o]        = even;
    out[o + 128u] = odd;   // odd row: +512 floats = +128 float4s
}

extern "C" void kernel_launch(void* const* d_in, const int* in_sizes, int n_in,
                              void* d_out, int out_size)
{
    const float2* A = (const float2*)d_in[0];
    const float2* H = (const float2*)d_in[1];
    const float2* V = (const float2*)d_in[2];
    const float2* D = (const float2*)d_in[3];
    float4* out = (float4*)d_out;

    const unsigned n_threads = (unsigned)(in_sizes[0] / 2);
    const unsigned blocks = (n_threads + 511u) / 512u;

    idwt2_haar_kernel<<<blocks, 512>>>(A, H, V, D, out);
}